// round 2
// baseline (speedup 1.0000x reference)
#include <cuda_runtime.h>
#include <cuda_bf16.h>

// Problem constants (B=1, L=1024, d_msa=256, d_pair=128, d_state=32, 36 RBF bins)
#define L 1024
#define DPAIR 128
#define DMSA 256
#define DSTATE 32
#define NBINS 36
#define JT 256           // j-tile per block in pair kernel

#define MSA_OFF   0
#define PAIR_OFF  (L * DMSA)                         // 262144
#define STATE_OFF (PAIR_OFF + (size_t)L * L * DPAIR) // 134479872

// ---- device scratch (static: no allocation) ----
__device__ float g_left [L * DPAIR];   // left proj + b_proj + b_pair folded in
__device__ float g_right[L * DPAIR];
__device__ float g_cb   [L * 4];       // Cb xyz (padded)
__device__ float g_Wd   [NBINS * DPAIR]; // W[:, :36] transposed -> [k][p]

// ------------------------------------------------------------------
// Kernel A0: transpose the RBF part of W into [k][p] layout
// ------------------------------------------------------------------
__global__ void wd_transpose_kernel(const float* __restrict__ W) {
    int idx = blockIdx.x * blockDim.x + threadIdx.x;   // k*128+p
    if (idx < NBINS * DPAIR) {
        int k = idx >> 7, p = idx & 127;
        g_Wd[idx] = W[p * 100 + k];
    }
}

// ------------------------------------------------------------------
// Kernel A: per-residue prep. Block = residue i, 128 threads.
//   - state layernorm -> out_state + smem
//   - left/right 32->128 GEMVs (b_proj + b_pair folded into left)
//   - Cb virtual atom
// ------------------------------------------------------------------
__global__ __launch_bounds__(128) void prep_kernel(
    const float* __restrict__ state, const float* __restrict__ xyz,
    const float* __restrict__ W, const float* __restrict__ b_proj,
    const float* __restrict__ g_state, const float* __restrict__ b_state,
    const float* __restrict__ b_pair, float* __restrict__ out_state)
{
    __shared__ float s_sn[DSTATE];
    __shared__ float sWl[128 * 65];   // W[:,36:100], padded stride 65 vs bank conflicts
    int i = blockIdx.x, tid = threadIdx.x;

    // stage W[:,36:100] into smem (coalesced 64-float row chunks)
    for (int idx = tid; idx < 128 * 64; idx += 128) {
        int p = idx >> 6, k = idx & 63;
        sWl[p * 65 + k] = W[p * 100 + 36 + k];
    }

    if (tid < 32) {
        float x = state[i * DSTATE + tid];
        float s1 = x, s2 = x * x;
        #pragma unroll
        for (int o = 16; o; o >>= 1) {
            s1 += __shfl_xor_sync(0xffffffffu, s1, o);
            s2 += __shfl_xor_sync(0xffffffffu, s2, o);
        }
        float m   = s1 * (1.0f / 32.0f);
        float var = fmaf(-m, m, s2 * (1.0f / 32.0f));
        float sn  = (x - m) * rsqrtf(var + 1e-5f) * g_state[tid] + b_state[tid];
        s_sn[tid] = sn;
        out_state[i * DSTATE + tid] = sn;
    }
    __syncthreads();

    int p = tid;  // 0..127 output channel
    float l = b_proj[p] + b_pair[p];
    float r = 0.0f;
    #pragma unroll
    for (int k = 0; k < 32; k++) {
        float s = s_sn[k];
        l = fmaf(s, sWl[p * 65 + k],      l);
        r = fmaf(s, sWl[p * 65 + 32 + k], r);
    }
    g_left [i * DPAIR + p] = l;
    g_right[i * DPAIR + p] = r;

    if (tid == 0) {
        const float* q = xyz + i * 9;
        float bx = q[3] - q[0], by = q[4] - q[1], bz = q[5] - q[2];  // Ca - N
        float cx = q[6] - q[3], cy = q[7] - q[4], cz = q[8] - q[5];  // C - Ca
        float ax = by * cz - bz * cy;
        float ay = bz * cx - bx * cz;
        float az = bx * cy - by * cx;
        g_cb[i * 4 + 0] = -0.58273431f * ax + 0.56802827f * bx - 0.54067466f * cx + q[3];
        g_cb[i * 4 + 1] = -0.58273431f * ay + 0.56802827f * by - 0.54067466f * cy + q[4];
        g_cb[i * 4 + 2] = -0.58273431f * az + 0.56802827f * bz - 0.54067466f * cz + q[5];
    }
}

// ------------------------------------------------------------------
// Kernel B: msa layernorm (1024 rows x 256). Warp per row, 8 ch/lane.
// ------------------------------------------------------------------
__global__ __launch_bounds__(256) void msa_kernel(
    const float* __restrict__ msa, const float* __restrict__ g,
    const float* __restrict__ b, float* __restrict__ out)
{
    int w = threadIdx.x >> 5, lane = threadIdx.x & 31;
    int r = blockIdx.x * 8 + w;
    const float4* row = (const float4*)(msa + (size_t)r * DMSA);
    float4 a0 = row[lane], a1 = row[lane + 32];
    float s1 = a0.x + a0.y + a0.z + a0.w + a1.x + a1.y + a1.z + a1.w;
    float s2 = a0.x * a0.x + a0.y * a0.y + a0.z * a0.z + a0.w * a0.w
             + a1.x * a1.x + a1.y * a1.y + a1.z * a1.z + a1.w * a1.w;
    #pragma unroll
    for (int o = 16; o; o >>= 1) {
        s1 += __shfl_xor_sync(0xffffffffu, s1, o);
        s2 += __shfl_xor_sync(0xffffffffu, s2, o);
    }
    float m    = s1 * (1.0f / 256.0f);
    float var  = fmaf(-m, m, s2 * (1.0f / 256.0f));
    float rstd = rsqrtf(var + 1e-5f);
    const float4* G4 = (const float4*)g;
    const float4* B4 = (const float4*)b;
    float4 G0 = G4[lane], G1 = G4[lane + 32];
    float4 B0 = B4[lane], B1 = B4[lane + 32];
    float4 o0, o1;
    o0.x = fmaf((a0.x - m) * rstd, G0.x, B0.x);
    o0.y = fmaf((a0.y - m) * rstd, G0.y, B0.y);
    o0.z = fmaf((a0.z - m) * rstd, G0.z, B0.z);
    o0.w = fmaf((a0.w - m) * rstd, G0.w, B0.w);
    o1.x = fmaf((a1.x - m) * rstd, G1.x, B1.x);
    o1.y = fmaf((a1.y - m) * rstd, G1.y, B1.y);
    o1.z = fmaf((a1.z - m) * rstd, G1.z, B1.z);
    o1.w = fmaf((a1.w - m) * rstd, G1.w, B1.w);
    float4* orow = (float4*)(out + (size_t)r * DMSA);
    orow[lane] = o0; orow[lane + 32] = o1;
}

// ------------------------------------------------------------------
// Kernel C: main pair kernel. Block = (jtile, i). 256 thr, warp/pair,
// 4 channels/lane. 7-tap windowed RBF dot from smem W; feats precomputed
// cooperatively. Streaming loads/stores for the bulk pair tensor.
// ------------------------------------------------------------------
__global__ __launch_bounds__(256, 3) void pair_kernel(
    const float* __restrict__ pair, const float* __restrict__ g_pair,
    float* __restrict__ out_pair)
{
    __shared__ float sW[NBINS * DPAIR];  // 18432 B
    __shared__ float sF[8 * JT];         // feats, tap-major: sF[m*JT + j]
    __shared__ int   sK[JT];

    int i   = blockIdx.y;
    int jt0 = blockIdx.x * JT;
    int tid = threadIdx.x;

    // stage transposed W_d
    for (int idx = tid; idx < NBINS * DPAIR / 4; idx += 256)
        ((float4*)sW)[idx] = ((const float4*)g_Wd)[idx];

    // cooperative feats: thread t handles pair (i, jt0+t)
    {
        int j = jt0 + tid;
        float dx = g_cb[i * 4 + 0] - g_cb[j * 4 + 0];
        float dy = g_cb[i * 4 + 1] - g_cb[j * 4 + 1];
        float dz = g_cb[i * 4 + 2] - g_cb[j * 4 + 2];
        float d2 = dx * dx + dy * dy + dz * dz;
        float D  = sqrtf(fmaxf(d2, 1e-12f));
        int k0   = __float2int_rn((D - 2.0f) * 1.75f);   // 35/20
        int klo  = min(max(k0 - 3, 0), 29);
        sK[tid]  = klo;
        #pragma unroll
        for (int m = 0; m < 7; m++) {
            float mu = 2.0f + (float)(klo + m) * (20.0f / 35.0f);
            float t  = (D - mu) * 1.8f;                  // 36/20
            sF[m * JT + tid] = __expf(-t * t);
        }
    }
    __syncthreads();

    int w = tid >> 5, lane = tid & 31;
    int jb = jt0 + w * 32;  // this warp's 32 consecutive j

    float4 Lf = *(const float4*)&g_left[i * DPAIR + lane * 4];  // incl b_proj+b_pair
    float4 G  = ((const float4*)g_pair)[lane];

    const float4* pin  = (const float4*)pair    + ((size_t)i * L + jb) * (DPAIR / 4) + lane;
    float4*       pout = (float4*)out_pair      + ((size_t)i * L + jb) * (DPAIR / 4) + lane;
    const float*  swb  = sW + lane * 4;

    // depth-2 software pipeline over 32 rows
    float4 cur = __ldcs(pin);
    float4 nxt = __ldcs(pin + 32);

    for (int jj = 0; jj < 32; ++jj) {
        float4 c = cur;
        cur = nxt;
        if (jj + 2 < 32) nxt = __ldcs(pin + (jj + 2) * 32);

        // layernorm stats over 128 channels (4/lane + butterfly)
        float s1 = c.x + c.y + c.z + c.w;
        float s2 = c.x * c.x + c.y * c.y + c.z * c.z + c.w * c.w;
        #pragma unroll
        for (int o = 16; o; o >>= 1) {
            s1 += __shfl_xor_sync(0xffffffffu, s1, o);
            s2 += __shfl_xor_sync(0xffffffffu, s2, o);
        }
        float m    = s1 * (1.0f / 128.0f);
        float var  = fmaf(-m, m, s2 * (1.0f / 128.0f));
        float rstd = rsqrtf(var + 1e-5f);

        int jl  = w * 32 + jj;
        int klo = sK[jl];

        const float4 R = *(const float4*)&g_right[(size_t)(jb + jj) * DPAIR + lane * 4];
        float4 acc;
        acc.x = Lf.x + R.x; acc.y = Lf.y + R.y;
        acc.z = Lf.z + R.z; acc.w = Lf.w + R.w;

        const float* wp = swb + klo * DPAIR;
        #pragma unroll
        for (int mt = 0; mt < 7; mt++) {
            float f = sF[mt * JT + jl];
            float4 wv = *(const float4*)(wp + mt * DPAIR);
            acc.x = fmaf(f, wv.x, acc.x);
            acc.y = fmaf(f, wv.y, acc.y);
            acc.z = fmaf(f, wv.z, acc.z);
            acc.w = fmaf(f, wv.w, acc.w);
        }

        float4 o;
        o.x = fmaf(c.x - m, rstd * G.x, acc.x);
        o.y = fmaf(c.y - m, rstd * G.y, acc.y);
        o.z = fmaf(c.z - m, rstd * G.z, acc.z);
        o.w = fmaf(c.w - m, rstd * G.w, acc.w);
        __stcs(pout + jj * 32, o);
    }
}

// ------------------------------------------------------------------
extern "C" void kernel_launch(void* const* d_in, const int* in_sizes, int n_in,
                              void* d_out, int out_size)
{
    // inputs: 0 seq, 1 msa, 2 pair, 3 xyz, 4 state, 5 W, 6 b_proj,
    //         7 g_state, 8 b_state, 9 g_pair, 10 b_pair, 11 g_msa, 12 b_msa
    const float* msa     = (const float*)d_in[1];
    const float* pair    = (const float*)d_in[2];
    const float* xyz     = (const float*)d_in[3];
    const float* state   = (const float*)d_in[4];
    const float* W       = (const float*)d_in[5];
    const float* b_proj  = (const float*)d_in[6];
    const float* g_state = (const float*)d_in[7];
    const float* b_state = (const float*)d_in[8];
    const float* g_pair  = (const float*)d_in[9];
    const float* b_pair  = (const float*)d_in[10];
    const float* g_msa   = (const float*)d_in[11];
    const float* b_msa   = (const float*)d_in[12];
    float* out = (float*)d_out;

    wd_transpose_kernel<<<(NBINS * DPAIR + 127) / 128, 128>>>(W);
    prep_kernel<<<L, 128>>>(state, xyz, W, b_proj, g_state, b_state, b_pair,
                            out + STATE_OFF);
    msa_kernel<<<L / 8, 256>>>(msa, g_msa, b_msa, out + MSA_OFF);
    pair_kernel<<<dim3(L / JT, L), 256>>>(pair, g_pair, out + PAIR_OFF);
}

// round 3
// speedup vs baseline: 1.1640x; 1.1640x over previous
#include <cuda_runtime.h>
#include <cuda_fp16.h>
#include <cuda_bf16.h>

// Problem constants (B=1, L=1024, d_msa=256, d_pair=128, d_state=32, 36 RBF bins)
#define L 1024
#define DPAIR 128
#define DMSA 256
#define DSTATE 32
#define JT 256           // j-tile per block in pair kernel
#define TABN 2048        // distance-table entries
#define TABH 0.0125f     // table spacing in D
#define TABSCL 80.0f     // 1/TABH

#define MSA_OFF   0
#define PAIR_OFF  (L * DMSA)                         // 262144
#define STATE_OFF (PAIR_OFF + (size_t)L * L * DPAIR) // 134479872

// ---- device scratch (static: no allocation) ----
__device__ float g_left [L * DPAIR];   // left proj + b_proj + b_pair folded in
__device__ float g_right[L * DPAIR];
__device__ float g_cb   [L * 4];       // Cb xyz (padded)
// g_tab[t*128+p] = half2( proj_p(t*h), proj_p((t+1)*h) )  -- 1 MB
__device__ __half2 g_tab[TABN * DPAIR];

struct alignas(16) h2x4 { __half2 a, b, c, d; };

// ------------------------------------------------------------------
// Kernel T: build the D -> proj[128] lookup table (exact 36-bin sum).
// ------------------------------------------------------------------
__global__ __launch_bounds__(256) void table_kernel(const float* __restrict__ W) {
    int idx = blockIdx.x * blockDim.x + threadIdx.x;   // t*128 + p
    int t = idx >> 7, p = idx & 127;
    float D0 = (float)t * TABH;
    float D1 = D0 + TABH;
    float s0 = 0.0f, s1 = 0.0f;
    #pragma unroll
    for (int k = 0; k < 36; k++) {
        float mu = 2.0f + (float)k * (20.0f / 35.0f);   // linspace(2,22,36)
        float w  = W[p * 100 + k];
        float a0 = (D0 - mu) * 1.8f;                    // 1/sigma = 36/20
        float a1 = (D1 - mu) * 1.8f;
        s0 = fmaf(__expf(-a0 * a0), w, s0);
        s1 = fmaf(__expf(-a1 * a1), w, s1);
    }
    g_tab[idx] = __floats2half2_rn(s0, s1);
}

// ------------------------------------------------------------------
// Kernel A: per-residue prep. Block = residue i, 128 threads.
//   - state layernorm -> out_state + smem
//   - left/right 32->128 GEMVs (b_proj + b_pair folded into left)
//   - Cb virtual atom
// ------------------------------------------------------------------
__global__ __launch_bounds__(128) void prep_kernel(
    const float* __restrict__ state, const float* __restrict__ xyz,
    const float* __restrict__ W, const float* __restrict__ b_proj,
    const float* __restrict__ g_state, const float* __restrict__ b_state,
    const float* __restrict__ b_pair, float* __restrict__ out_state)
{
    __shared__ float s_sn[DSTATE];
    __shared__ float sWl[128 * 65];   // W[:,36:100], padded stride
    int i = blockIdx.x, tid = threadIdx.x;

    for (int idx = tid; idx < 128 * 64; idx += 128) {
        int p = idx >> 6, k = idx & 63;
        sWl[p * 65 + k] = W[p * 100 + 36 + k];
    }

    if (tid < 32) {
        float x = state[i * DSTATE + tid];
        float s1 = x, s2 = x * x;
        #pragma unroll
        for (int o = 16; o; o >>= 1) {
            s1 += __shfl_xor_sync(0xffffffffu, s1, o);
            s2 += __shfl_xor_sync(0xffffffffu, s2, o);
        }
        float m   = s1 * (1.0f / 32.0f);
        float var = fmaf(-m, m, s2 * (1.0f / 32.0f));
        float sn  = (x - m) * rsqrtf(var + 1e-5f) * g_state[tid] + b_state[tid];
        s_sn[tid] = sn;
        out_state[i * DSTATE + tid] = sn;
    }
    __syncthreads();

    int p = tid;
    float l = b_proj[p] + b_pair[p];
    float r = 0.0f;
    #pragma unroll
    for (int k = 0; k < 32; k++) {
        float s = s_sn[k];
        l = fmaf(s, sWl[p * 65 + k],      l);
        r = fmaf(s, sWl[p * 65 + 32 + k], r);
    }
    g_left [i * DPAIR + p] = l;
    g_right[i * DPAIR + p] = r;

    if (tid == 0) {
        const float* q = xyz + i * 9;
        float bx = q[3] - q[0], by = q[4] - q[1], bz = q[5] - q[2];
        float cx = q[6] - q[3], cy = q[7] - q[4], cz = q[8] - q[5];
        float ax = by * cz - bz * cy;
        float ay = bz * cx - bx * cz;
        float az = bx * cy - by * cx;
        g_cb[i * 4 + 0] = -0.58273431f * ax + 0.56802827f * bx - 0.54067466f * cx + q[3];
        g_cb[i * 4 + 1] = -0.58273431f * ay + 0.56802827f * by - 0.54067466f * cy + q[4];
        g_cb[i * 4 + 2] = -0.58273431f * az + 0.56802827f * bz - 0.54067466f * cz + q[5];
    }
}

// ------------------------------------------------------------------
// Kernel B: msa layernorm (1024 rows x 256). Warp per row.
// ------------------------------------------------------------------
__global__ __launch_bounds__(256) void msa_kernel(
    const float* __restrict__ msa, const float* __restrict__ g,
    const float* __restrict__ b, float* __restrict__ out)
{
    int w = threadIdx.x >> 5, lane = threadIdx.x & 31;
    int r = blockIdx.x * 8 + w;
    const float4* row = (const float4*)(msa + (size_t)r * DMSA);
    float4 a0 = row[lane], a1 = row[lane + 32];
    float s1 = a0.x + a0.y + a0.z + a0.w + a1.x + a1.y + a1.z + a1.w;
    float s2 = a0.x * a0.x + a0.y * a0.y + a0.z * a0.z + a0.w * a0.w
             + a1.x * a1.x + a1.y * a1.y + a1.z * a1.z + a1.w * a1.w;
    #pragma unroll
    for (int o = 16; o; o >>= 1) {
        s1 += __shfl_xor_sync(0xffffffffu, s1, o);
        s2 += __shfl_xor_sync(0xffffffffu, s2, o);
    }
    float m    = s1 * (1.0f / 256.0f);
    float var  = fmaf(-m, m, s2 * (1.0f / 256.0f));
    float rstd = rsqrtf(var + 1e-5f);
    const float4* G4 = (const float4*)g;
    const float4* B4 = (const float4*)b;
    float4 G0 = G4[lane], G1 = G4[lane + 32];
    float4 B0 = B4[lane], B1 = B4[lane + 32];
    float4 o0, o1;
    o0.x = fmaf((a0.x - m) * rstd, G0.x, B0.x);
    o0.y = fmaf((a0.y - m) * rstd, G0.y, B0.y);
    o0.z = fmaf((a0.z - m) * rstd, G0.z, B0.z);
    o0.w = fmaf((a0.w - m) * rstd, G0.w, B0.w);
    o1.x = fmaf((a1.x - m) * rstd, G1.x, B1.x);
    o1.y = fmaf((a1.y - m) * rstd, G1.y, B1.y);
    o1.z = fmaf((a1.z - m) * rstd, G1.z, B1.z);
    o1.w = fmaf((a1.w - m) * rstd, G1.w, B1.w);
    float4* orow = (float4*)(out + (size_t)r * DMSA);
    orow[lane] = o0; orow[lane + 32] = o1;
}

// ------------------------------------------------------------------
// Kernel C: main pair kernel. Block = (i, jtile); blockIdx.x = i is
// fastest so consecutive blocks on an SM share the jtile (keeps the
// 128 KB right-tile hot in L1). Warp per pair, 4 channels/lane.
// RBF projection = half2 table lerp: ONE LDG.128 per lane per pair.
// Pair tensor streamed with __ldcs/__stcs (evict-first).
// ------------------------------------------------------------------
__global__ __launch_bounds__(256, 4) void pair_kernel(
    const float* __restrict__ pair, const float* __restrict__ g_pair,
    float* __restrict__ out_pair)
{
    __shared__ float sU[JT];   // clamped table coordinate per j

    int i   = blockIdx.x;
    int jt0 = blockIdx.y * JT;
    int tid = threadIdx.x;

    // cooperative distance -> table coordinate (thread t handles j = jt0+t)
    {
        int j = jt0 + tid;
        float dx = g_cb[i * 4 + 0] - g_cb[j * 4 + 0];
        float dy = g_cb[i * 4 + 1] - g_cb[j * 4 + 1];
        float dz = g_cb[i * 4 + 2] - g_cb[j * 4 + 2];
        float d2 = dx * dx + dy * dy + dz * dz;
        float D  = sqrtf(fmaxf(d2, 1e-12f));
        sU[tid]  = fminf(D * TABSCL, 2046.999f);
    }
    __syncthreads();

    int w = tid >> 5, lane = tid & 31;
    int jb  = jt0 + w * 32;   // this warp's 32 consecutive j
    int jlb = w * 32;

    float4 Lf = *(const float4*)&g_left[i * DPAIR + lane * 4];  // incl biases
    float4 G  = ((const float4*)g_pair)[lane];

    const float4* pin  = (const float4*)pair    + ((size_t)i * L + jb) * (DPAIR / 4) + lane;
    float4*       pout = (float4*)out_pair      + ((size_t)i * L + jb) * (DPAIR / 4) + lane;

    // ---- prologue: prefetch row 0 (right + table) and rows 0,1 of pair ----
    float u0 = sU[jlb];
    int   t0 = (int)u0;
    float fc = u0 - (float)t0;
    h2x4  Tc = *(const h2x4*)(g_tab + t0 * DPAIR + lane * 4);
    float4 Rc = *(const float4*)&g_right[(size_t)jb * DPAIR + lane * 4];
    float4 Pc = __ldcs(pin);
    float4 Pn = __ldcs(pin + 32);

    #pragma unroll 4
    for (int jj = 0; jj < 32; ++jj) {
        // prefetch next row's right + table, and pair two ahead
        float fn = fc; h2x4 Tn = Tc; float4 Rn = Rc;
        if (jj + 1 < 32) {
            float u = sU[jlb + jj + 1];
            int   t = (int)u;
            fn = u - (float)t;
            Tn = *(const h2x4*)(g_tab + t * DPAIR + lane * 4);
            Rn = *(const float4*)&g_right[(size_t)(jb + jj + 1) * DPAIR + lane * 4];
        }
        float4 c = Pc;
        Pc = Pn;
        if (jj + 2 < 32) Pn = __ldcs(pin + (jj + 2) * 32);

        // layernorm stats over 128 channels (4/lane + butterfly)
        float s1 = c.x + c.y + c.z + c.w;
        float s2 = c.x * c.x + c.y * c.y + c.z * c.z + c.w * c.w;
        #pragma unroll
        for (int o = 16; o; o >>= 1) {
            s1 += __shfl_xor_sync(0xffffffffu, s1, o);
            s2 += __shfl_xor_sync(0xffffffffu, s2, o);
        }
        float m    = s1 * (1.0f / 128.0f);
        float var  = fmaf(-m, m, s2 * (1.0f / 128.0f));
        float rstd = rsqrtf(var + 1e-5f);

        // proj via table lerp + left + right
        float2 p0 = __half22float2(Tc.a);
        float2 p1 = __half22float2(Tc.b);
        float2 p2 = __half22float2(Tc.c);
        float2 p3 = __half22float2(Tc.d);
        float4 acc;
        acc.x = Lf.x + Rc.x + fmaf(fc, p0.y - p0.x, p0.x);
        acc.y = Lf.y + Rc.y + fmaf(fc, p1.y - p1.x, p1.x);
        acc.z = Lf.z + Rc.z + fmaf(fc, p2.y - p2.x, p2.x);
        acc.w = Lf.w + Rc.w + fmaf(fc, p3.y - p3.x, p3.x);

        float4 o;
        o.x = fmaf(c.x - m, rstd * G.x, acc.x);
        o.y = fmaf(c.y - m, rstd * G.y, acc.y);
        o.z = fmaf(c.z - m, rstd * G.z, acc.z);
        o.w = fmaf(c.w - m, rstd * G.w, acc.w);
        __stcs(pout + jj * 32, o);

        fc = fn; Tc = Tn; Rc = Rn;
    }
}

// ------------------------------------------------------------------
extern "C" void kernel_launch(void* const* d_in, const int* in_sizes, int n_in,
                              void* d_out, int out_size)
{
    // inputs: 0 seq, 1 msa, 2 pair, 3 xyz, 4 state, 5 W, 6 b_proj,
    //         7 g_state, 8 b_state, 9 g_pair, 10 b_pair, 11 g_msa, 12 b_msa
    const float* msa     = (const float*)d_in[1];
    const float* pair    = (const float*)d_in[2];
    const float* xyz     = (const float*)d_in[3];
    const float* state   = (const float*)d_in[4];
    const float* W       = (const float*)d_in[5];
    const float* b_proj  = (const float*)d_in[6];
    const float* g_state = (const float*)d_in[7];
    const float* b_state = (const float*)d_in[8];
    const float* g_pair  = (const float*)d_in[9];
    const float* b_pair  = (const float*)d_in[10];
    const float* g_msa   = (const float*)d_in[11];
    const float* b_msa   = (const float*)d_in[12];
    float* out = (float*)d_out;

    table_kernel<<<TABN * DPAIR / 256, 256>>>(W);
    prep_kernel<<<L, 128>>>(state, xyz, W, b_proj, g_state, b_state, b_pair,
                            out + STATE_OFF);
    msa_kernel<<<L / 8, 256>>>(msa, g_msa, b_msa, out + MSA_OFF);
    pair_kernel<<<dim3(L, L / JT), 256>>>(pair, g_pair, out + PAIR_OFF);
}

// round 5
// speedup vs baseline: 1.1718x; 1.0067x over previous
#include <cuda_runtime.h>
#include <cuda_fp16.h>
#include <cuda_bf16.h>

// Problem constants (B=1, L=1024, d_msa=256, d_pair=128, d_state=32, 36 RBF bins)
#define L 1024
#define DPAIR 128
#define DMSA 256
#define DSTATE 32
#define JT 256           // j-tile per block in pair kernel
#define TABN 2048        // distance-table entries
#define TABH 0.0125f     // table spacing in D
#define TABSCL 80.0f     // 1/TABH

#define MSA_OFF   0
#define PAIR_OFF  (L * DMSA)                         // 262144
#define STATE_OFF (PAIR_OFF + (size_t)L * L * DPAIR) // 134479872

// fixed-point scales for warp reductions of LN partials
#define S1SCL 32768.0f        // 2^15 for sum(x) partials (|partial| ~ 24)
#define S1INV (1.0f / 32768.0f)
#define S2SCL 8192.0f         // 2^13 for sum(x^2) partials (partial ~ 150)
#define S2INV (1.0f / 8192.0f)

// ---- device scratch (static: no allocation) ----
__device__ float g_left [L * DPAIR];   // left proj + b_proj + b_pair folded in
__device__ float g_right[L * DPAIR];
__device__ float g_cb   [L * 4];       // Cb xyz (padded)
// g_tab[t*128+p] = half2( proj_p(t*h), proj_p((t+1)*h) )  -- 1 MB
__device__ __half2 g_tab[TABN * DPAIR];

struct alignas(16) h2x4 { __half2 a, b, c, d; };

// classic butterfly (for the small kernels)
__device__ __forceinline__ float warp_sum_shfl(float v) {
    #pragma unroll
    for (int o = 16; o; o >>= 1) v += __shfl_xor_sync(0xffffffffu, v, o);
    return v;
}

// ------------------------------------------------------------------
// Kernel T: build the D -> proj[128] lookup table (exact 36-bin sum).
// ------------------------------------------------------------------
__global__ __launch_bounds__(256) void table_kernel(const float* __restrict__ W) {
    int idx = blockIdx.x * blockDim.x + threadIdx.x;   // t*128 + p
    int t = idx >> 7, p = idx & 127;
    float D0 = (float)t * TABH;
    float D1 = D0 + TABH;
    float s0 = 0.0f, s1 = 0.0f;
    #pragma unroll
    for (int k = 0; k < 36; k++) {
        float mu = 2.0f + (float)k * (20.0f / 35.0f);   // linspace(2,22,36)
        float w  = W[p * 100 + k];
        float a0 = (D0 - mu) * 1.8f;                    // 1/sigma = 36/20
        float a1 = (D1 - mu) * 1.8f;
        s0 = fmaf(__expf(-a0 * a0), w, s0);
        s1 = fmaf(__expf(-a1 * a1), w, s1);
    }
    g_tab[idx] = __floats2half2_rn(s0, s1);
}

// ------------------------------------------------------------------
// Kernel A: per-residue prep. Block = residue i, 128 threads.
//   - state layernorm -> out_state + smem
//   - left/right 32->128 GEMVs (b_proj + b_pair folded into left)
//   - Cb virtual atom
// ------------------------------------------------------------------
__global__ __launch_bounds__(128) void prep_kernel(
    const float* __restrict__ state, const float* __restrict__ xyz,
    const float* __restrict__ W, const float* __restrict__ b_proj,
    const float* __restrict__ g_state, const float* __restrict__ b_state,
    const float* __restrict__ b_pair, float* __restrict__ out_state)
{
    __shared__ float s_sn[DSTATE];
    __shared__ float sWl[128 * 65];   // W[:,36:100], padded stride
    int i = blockIdx.x, tid = threadIdx.x;

    for (int idx = tid; idx < 128 * 64; idx += 128) {
        int p = idx >> 6, k = idx & 63;
        sWl[p * 65 + k] = W[p * 100 + 36 + k];
    }

    if (tid < 32) {
        float x = state[i * DSTATE + tid];
        float s1 = warp_sum_shfl(x);
        float s2 = warp_sum_shfl(x * x);
        float m   = s1 * (1.0f / 32.0f);
        float var = fmaf(-m, m, s2 * (1.0f / 32.0f));
        float sn  = (x - m) * rsqrtf(var + 1e-5f) * g_state[tid] + b_state[tid];
        s_sn[tid] = sn;
        out_state[i * DSTATE + tid] = sn;
    }
    __syncthreads();

    int p = tid;
    float l = b_proj[p] + b_pair[p];
    float r = 0.0f;
    #pragma unroll
    for (int k = 0; k < 32; k++) {
        float s = s_sn[k];
        l = fmaf(s, sWl[p * 65 + k],      l);
        r = fmaf(s, sWl[p * 65 + 32 + k], r);
    }
    g_left [i * DPAIR + p] = l;
    g_right[i * DPAIR + p] = r;

    if (tid == 0) {
        const float* q = xyz + i * 9;
        float bx = q[3] - q[0], by = q[4] - q[1], bz = q[5] - q[2];
        float cx = q[6] - q[3], cy = q[7] - q[4], cz = q[8] - q[5];
        float ax = by * cz - bz * cy;
        float ay = bz * cx - bx * cz;
        float az = bx * cy - by * cx;
        g_cb[i * 4 + 0] = -0.58273431f * ax + 0.56802827f * bx - 0.54067466f * cx + q[3];
        g_cb[i * 4 + 1] = -0.58273431f * ay + 0.56802827f * by - 0.54067466f * cy + q[4];
        g_cb[i * 4 + 2] = -0.58273431f * az + 0.56802827f * bz - 0.54067466f * cz + q[5];
    }
}

// ------------------------------------------------------------------
// Kernel B: msa layernorm (1024 rows x 256). Warp per row.
// ------------------------------------------------------------------
__global__ __launch_bounds__(256) void msa_kernel(
    const float* __restrict__ msa, const float* __restrict__ g,
    const float* __restrict__ b, float* __restrict__ out)
{
    int w = threadIdx.x >> 5, lane = threadIdx.x & 31;
    int r = blockIdx.x * 8 + w;
    const float4* row = (const float4*)(msa + (size_t)r * DMSA);
    float4 a0 = row[lane], a1 = row[lane + 32];
    float s1 = warp_sum_shfl(a0.x + a0.y + a0.z + a0.w + a1.x + a1.y + a1.z + a1.w);
    float s2 = warp_sum_shfl(a0.x * a0.x + a0.y * a0.y + a0.z * a0.z + a0.w * a0.w
                           + a1.x * a1.x + a1.y * a1.y + a1.z * a1.z + a1.w * a1.w);
    float m    = s1 * (1.0f / 256.0f);
    float var  = fmaf(-m, m, s2 * (1.0f / 256.0f));
    float rstd = rsqrtf(var + 1e-5f);
    const float4* G4 = (const float4*)g;
    const float4* B4 = (const float4*)b;
    float4 G0 = G4[lane], G1 = G4[lane + 32];
    float4 B0 = B4[lane], B1 = B4[lane + 32];
    float4 o0, o1;
    o0.x = fmaf((a0.x - m) * rstd, G0.x, B0.x);
    o0.y = fmaf((a0.y - m) * rstd, G0.y, B0.y);
    o0.z = fmaf((a0.z - m) * rstd, G0.z, B0.z);
    o0.w = fmaf((a0.w - m) * rstd, G0.w, B0.w);
    o1.x = fmaf((a1.x - m) * rstd, G1.x, B1.x);
    o1.y = fmaf((a1.y - m) * rstd, G1.y, B1.y);
    o1.z = fmaf((a1.z - m) * rstd, G1.z, B1.z);
    o1.w = fmaf((a1.w - m) * rstd, G1.w, B1.w);
    float4* orow = (float4*)(out + (size_t)r * DMSA);
    orow[lane] = o0; orow[lane + 32] = o1;
}

// ------------------------------------------------------------------
// Kernel C: main pair kernel. Block = (i, jtile); blockIdx.x = i is
// fastest so consecutive blocks on an SM share the jtile (keeps the
// right-tile + table hot). Warp per pair, 4 channels/lane.
// RBF projection = half2 table lerp: ONE LDG.128 per lane per pair.
// Layernorm stats: fixed-point REDUX.SUM (2 LSU ops) instead of 10 SHFL.
// Pair tensor streamed with __ldcs/__stcs (evict-first).
// ------------------------------------------------------------------
__global__ __launch_bounds__(256, 4) void pair_kernel(
    const float* __restrict__ pair, const float* __restrict__ g_pair,
    float* __restrict__ out_pair)
{
    __shared__ float sU[JT];   // clamped table coordinate per j

    int i   = blockIdx.x;
    int jt0 = blockIdx.y * JT;
    int tid = threadIdx.x;

    // cooperative distance -> table coordinate (thread t handles j = jt0+t)
    {
        int j = jt0 + tid;
        float dx = g_cb[i * 4 + 0] - g_cb[j * 4 + 0];
        float dy = g_cb[i * 4 + 1] - g_cb[j * 4 + 1];
        float dz = g_cb[i * 4 + 2] - g_cb[j * 4 + 2];
        float d2 = dx * dx + dy * dy + dz * dz;
        float D  = sqrtf(fmaxf(d2, 1e-12f));
        sU[tid]  = fminf(D * TABSCL, 2046.999f);
    }
    __syncthreads();

    int w = tid >> 5, lane = tid & 31;
    int jb  = jt0 + w * 32;   // this warp's 32 consecutive j
    int jlb = w * 32;

    float4 Lf = *(const float4*)&g_left[i * DPAIR + lane * 4];  // incl biases
    float4 G  = ((const float4*)g_pair)[lane];

    const float4* pin  = (const float4*)pair    + ((size_t)i * L + jb) * (DPAIR / 4) + lane;
    float4*       pout = (float4*)out_pair      + ((size_t)i * L + jb) * (DPAIR / 4) + lane;

    // ---- prologue: prefetch row 0 (right + table) and rows 0,1 of pair ----
    float u0 = sU[jlb];
    int   t0 = (int)u0;
    float fc = u0 - (float)t0;
    h2x4  Tc = *(const h2x4*)(g_tab + t0 * DPAIR + lane * 4);
    float4 Rc = *(const float4*)&g_right[(size_t)jb * DPAIR + lane * 4];
    float4 Pc = __ldcs(pin);
    float4 Pn = __ldcs(pin + 32);

    #pragma unroll 4
    for (int jj = 0; jj < 32; ++jj) {
        // prefetch next row's right + table, and pair two ahead
        float fn = fc; h2x4 Tn = Tc; float4 Rn = Rc;
        if (jj + 1 < 32) {
            float u = sU[jlb + jj + 1];
            int   t = (int)u;
            fn = u - (float)t;
            Tn = *(const h2x4*)(g_tab + t * DPAIR + lane * 4);
            Rn = *(const float4*)&g_right[(size_t)(jb + jj + 1) * DPAIR + lane * 4];
        }
        float4 c = Pc;
        Pc = Pn;
        if (jj + 2 < 32) Pn = __ldcs(pin + (jj + 2) * 32);

        // layernorm stats over 128 channels: quantized partials + REDUX.SUM
        float p1 = c.x + c.y + c.z + c.w;
        float p2 = c.x * c.x + c.y * c.y + c.z * c.z + c.w * c.w;
        int i1 = __reduce_add_sync(0xffffffffu, __float2int_rn(p1 * S1SCL));
        int i2 = __reduce_add_sync(0xffffffffu, __float2int_rn(p2 * S2SCL));
        float s1 = (float)i1 * S1INV;
        float s2 = (float)i2 * S2INV;
        float m    = s1 * (1.0f / 128.0f);
        float var  = fmaf(-m, m, s2 * (1.0f / 128.0f));
        float rstd = rsqrtf(var + 1e-5f);

        // proj via table lerp + left + right
        float2 q0 = __half22float2(Tc.a);
        float2 q1 = __half22float2(Tc.b);
        float2 q2 = __half22float2(Tc.c);
        float2 q3 = __half22float2(Tc.d);
        float4 acc;
        acc.x = Lf.x + Rc.x + fmaf(fc, q0.y - q0.x, q0.x);
        acc.y = Lf.y + Rc.y + fmaf(fc, q1.y - q1.x, q1.x);
        acc.z = Lf.z + Rc.z + fmaf(fc, q2.y - q2.x, q2.x);
        acc.w = Lf.w + Rc.w + fmaf(fc, q3.y - q3.x, q3.x);

        float4 o;
        o.x = fmaf(c.x - m, rstd * G.x, acc.x);
        o.y = fmaf(c.y - m, rstd * G.y, acc.y);
        o.z = fmaf(c.z - m, rstd * G.z, acc.z);
        o.w = fmaf(c.w - m, rstd * G.w, acc.w);
        __stcs(pout + jj * 32, o);

        fc = fn; Tc = Tn; Rc = Rn;
    }
}

// ------------------------------------------------------------------
extern "C" void kernel_launch(void* const* d_in, const int* in_sizes, int n_in,
                              void* d_out, int out_size)
{
    // inputs: 0 seq, 1 msa, 2 pair, 3 xyz, 4 state, 5 W, 6 b_proj,
    //         7 g_state, 8 b_state, 9 g_pair, 10 b_pair, 11 g_msa, 12 b_msa
    const float* msa     = (const float*)d_in[1];
    const float* pair    = (const float*)d_in[2];
    const float* xyz     = (const float*)d_in[3];
    const float* state   = (const float*)d_in[4];
    const float* W       = (const float*)d_in[5];
    const float* b_proj  = (const float*)d_in[6];
    const float* g_state = (const float*)d_in[7];
    const float* b_state = (const float*)d_in[8];
    const float* g_pair  = (const float*)d_in[9];
    const float* b_pair  = (const float*)d_in[10];
    const float* g_msa   = (const float*)d_in[11];
    const float* b_msa   = (const float*)d_in[12];
    float* out = (float*)d_out;

    table_kernel<<<TABN * DPAIR / 256, 256>>>(W);
    prep_kernel<<<L, 128>>>(state, xyz, W, b_proj, g_state, b_state, b_pair,
                            out + STATE_OFF);
    msa_kernel<<<L / 8, 256>>>(msa, g_msa, b_msa, out + MSA_OFF);
    pair_kernel<<<dim3(L, L / JT), 256>>>(pair, g_pair, out + PAIR_OFF);
}

// round 6
// speedup vs baseline: 1.1822x; 1.0089x over previous
#include <cuda_runtime.h>
#include <cuda_fp16.h>
#include <cuda_bf16.h>

// Problem constants (B=1, L=1024, d_msa=256, d_pair=128, d_state=32, 36 RBF bins)
#define L 1024
#define DPAIR 128
#define DMSA 256
#define DSTATE 32
#define JT 256           // j-tile per block in pair kernel
#define TABN 2048        // distance-table entries
#define TABH 0.0125f     // table spacing in D
#define TABSCL 80.0f     // 1/TABH

#define MSA_OFF   0
#define PAIR_OFF  (L * DMSA)                         // 262144
#define STATE_OFF (PAIR_OFF + (size_t)L * L * DPAIR) // 134479872

// fixed-point scales for warp reductions of LN partials
#define S1SCL 32768.0f        // 2^15 for sum(x) partials (|partial| ~ 24)
#define S1INV (1.0f / 32768.0f)
#define S2SCL 8192.0f         // 2^13 for sum(x^2) partials (partial ~ 150)
#define S2INV (1.0f / 8192.0f)

// ---- device scratch (static: no allocation) ----
__device__ float g_left [L * DPAIR];   // left proj + b_proj + b_pair folded in
__device__ float g_right[L * DPAIR];
__device__ float g_cb   [L * 4];       // Cb xyz (padded)
// g_tab[t*128+p] = half2( proj_p(t*h), proj_p((t+1)*h) )  -- 1 MB
__device__ __half2 g_tab[TABN * DPAIR];

struct alignas(16) h2x4 { __half2 a, b, c, d; };

// classic butterfly (for the small kernels)
__device__ __forceinline__ float warp_sum_shfl(float v) {
    #pragma unroll
    for (int o = 16; o; o >>= 1) v += __shfl_xor_sync(0xffffffffu, v, o);
    return v;
}

// ------------------------------------------------------------------
// Kernel T: build the D -> proj[128] lookup table (exact 36-bin sum).
// ------------------------------------------------------------------
__global__ __launch_bounds__(256) void table_kernel(const float* __restrict__ W) {
    int idx = blockIdx.x * blockDim.x + threadIdx.x;   // t*128 + p
    int t = idx >> 7, p = idx & 127;
    float D0 = (float)t * TABH;
    float D1 = D0 + TABH;
    float s0 = 0.0f, s1 = 0.0f;
    #pragma unroll
    for (int k = 0; k < 36; k++) {
        float mu = 2.0f + (float)k * (20.0f / 35.0f);   // linspace(2,22,36)
        float w  = W[p * 100 + k];
        float a0 = (D0 - mu) * 1.8f;                    // 1/sigma = 36/20
        float a1 = (D1 - mu) * 1.8f;
        s0 = fmaf(__expf(-a0 * a0), w, s0);
        s1 = fmaf(__expf(-a1 * a1), w, s1);
    }
    g_tab[idx] = __floats2half2_rn(s0, s1);
}

// ------------------------------------------------------------------
// Kernel A: per-residue prep. Block = residue i, 128 threads.
//   - state layernorm -> out_state + smem
//   - left/right 32->128 GEMVs (b_proj + b_pair folded into left)
//   - Cb virtual atom
// ------------------------------------------------------------------
__global__ __launch_bounds__(128) void prep_kernel(
    const float* __restrict__ state, const float* __restrict__ xyz,
    const float* __restrict__ W, const float* __restrict__ b_proj,
    const float* __restrict__ g_state, const float* __restrict__ b_state,
    const float* __restrict__ b_pair, float* __restrict__ out_state)
{
    __shared__ float s_sn[DSTATE];
    __shared__ float sWl[128 * 65];   // W[:,36:100], padded stride
    int i = blockIdx.x, tid = threadIdx.x;

    for (int idx = tid; idx < 128 * 64; idx += 128) {
        int p = idx >> 6, k = idx & 63;
        sWl[p * 65 + k] = W[p * 100 + 36 + k];
    }

    if (tid < 32) {
        float x = state[i * DSTATE + tid];
        float s1 = warp_sum_shfl(x);
        float s2 = warp_sum_shfl(x * x);
        float m   = s1 * (1.0f / 32.0f);
        float var = fmaf(-m, m, s2 * (1.0f / 32.0f));
        float sn  = (x - m) * rsqrtf(var + 1e-5f) * g_state[tid] + b_state[tid];
        s_sn[tid] = sn;
        out_state[i * DSTATE + tid] = sn;
    }
    __syncthreads();

    int p = tid;
    float l = b_proj[p] + b_pair[p];
    float r = 0.0f;
    #pragma unroll
    for (int k = 0; k < 32; k++) {
        float s = s_sn[k];
        l = fmaf(s, sWl[p * 65 + k],      l);
        r = fmaf(s, sWl[p * 65 + 32 + k], r);
    }
    g_left [i * DPAIR + p] = l;
    g_right[i * DPAIR + p] = r;

    if (tid == 0) {
        const float* q = xyz + i * 9;
        float bx = q[3] - q[0], by = q[4] - q[1], bz = q[5] - q[2];
        float cx = q[6] - q[3], cy = q[7] - q[4], cz = q[8] - q[5];
        float ax = by * cz - bz * cy;
        float ay = bz * cx - bx * cz;
        float az = bx * cy - by * cx;
        g_cb[i * 4 + 0] = -0.58273431f * ax + 0.56802827f * bx - 0.54067466f * cx + q[3];
        g_cb[i * 4 + 1] = -0.58273431f * ay + 0.56802827f * by - 0.54067466f * cy + q[4];
        g_cb[i * 4 + 2] = -0.58273431f * az + 0.56802827f * bz - 0.54067466f * cz + q[5];
    }
}

// ------------------------------------------------------------------
// Kernel B: msa layernorm (1024 rows x 256). Warp per row.
// ------------------------------------------------------------------
__global__ __launch_bounds__(256) void msa_kernel(
    const float* __restrict__ msa, const float* __restrict__ g,
    const float* __restrict__ b, float* __restrict__ out)
{
    int w = threadIdx.x >> 5, lane = threadIdx.x & 31;
    int r = blockIdx.x * 8 + w;
    const float4* row = (const float4*)(msa + (size_t)r * DMSA);
    float4 a0 = row[lane], a1 = row[lane + 32];
    float s1 = warp_sum_shfl(a0.x + a0.y + a0.z + a0.w + a1.x + a1.y + a1.z + a1.w);
    float s2 = warp_sum_shfl(a0.x * a0.x + a0.y * a0.y + a0.z * a0.z + a0.w * a0.w
                           + a1.x * a1.x + a1.y * a1.y + a1.z * a1.z + a1.w * a1.w);
    float m    = s1 * (1.0f / 256.0f);
    float var  = fmaf(-m, m, s2 * (1.0f / 256.0f));
    float rstd = rsqrtf(var + 1e-5f);
    const float4* G4 = (const float4*)g;
    const float4* B4 = (const float4*)b;
    float4 G0 = G4[lane], G1 = G4[lane + 32];
    float4 B0 = B4[lane], B1 = B4[lane + 32];
    float4 o0, o1;
    o0.x = fmaf((a0.x - m) * rstd, G0.x, B0.x);
    o0.y = fmaf((a0.y - m) * rstd, G0.y, B0.y);
    o0.z = fmaf((a0.z - m) * rstd, G0.z, B0.z);
    o0.w = fmaf((a0.w - m) * rstd, G0.w, B0.w);
    o1.x = fmaf((a1.x - m) * rstd, G1.x, B1.x);
    o1.y = fmaf((a1.y - m) * rstd, G1.y, B1.y);
    o1.z = fmaf((a1.z - m) * rstd, G1.z, B1.z);
    o1.w = fmaf((a1.w - m) * rstd, G1.w, B1.w);
    float4* orow = (float4*)(out + (size_t)r * DMSA);
    orow[lane] = o0; orow[lane + 32] = o1;
}

// ------------------------------------------------------------------
// Kernel C: main pair kernel. Block = (i, jtile); blockIdx.x = i is
// fastest so consecutive blocks on an SM share the jtile (keeps the
// right-tile + table hot). Warp per pair, 4 channels/lane.
// RBF projection = half2 table lerp: ONE LDG.128 per lane per pair.
// Layernorm stats: fixed-point REDUX.SUM (2 LSU ops) instead of 10 SHFL.
// Pair tensor streamed with __ldcs/__stcs (evict-first).
// ------------------------------------------------------------------
__global__ __launch_bounds__(256, 4) void pair_kernel(
    const float* __restrict__ pair, const float* __restrict__ g_pair,
    float* __restrict__ out_pair)
{
    __shared__ float sU[JT];   // clamped table coordinate per j

    int i   = blockIdx.x;
    int jt0 = blockIdx.y * JT;
    int tid = threadIdx.x;

    // cooperative distance -> table coordinate (thread t handles j = jt0+t)
    {
        int j = jt0 + tid;
        float dx = g_cb[i * 4 + 0] - g_cb[j * 4 + 0];
        float dy = g_cb[i * 4 + 1] - g_cb[j * 4 + 1];
        float dz = g_cb[i * 4 + 2] - g_cb[j * 4 + 2];
        float d2 = dx * dx + dy * dy + dz * dz;
        float D  = sqrtf(fmaxf(d2, 1e-12f));
        sU[tid]  = fminf(D * TABSCL, 2046.999f);
    }
    __syncthreads();

    int w = tid >> 5, lane = tid & 31;
    int jb  = jt0 + w * 32;   // this warp's 32 consecutive j
    int jlb = w * 32;

    float4 Lf = *(const float4*)&g_left[i * DPAIR + lane * 4];  // incl biases
    float4 G  = ((const float4*)g_pair)[lane];

    const float4* pin  = (const float4*)pair    + ((size_t)i * L + jb) * (DPAIR / 4) + lane;
    float4*       pout = (float4*)out_pair      + ((size_t)i * L + jb) * (DPAIR / 4) + lane;

    // ---- prologue: prefetch row 0 (right + table) and rows 0,1 of pair ----
    float u0 = sU[jlb];
    int   t0 = (int)u0;
    float fc = u0 - (float)t0;
    h2x4  Tc = *(const h2x4*)(g_tab + t0 * DPAIR + lane * 4);
    float4 Rc = *(const float4*)&g_right[(size_t)jb * DPAIR + lane * 4];
    float4 Pc = __ldcs(pin);
    float4 Pn = __ldcs(pin + 32);

    #pragma unroll 4
    for (int jj = 0; jj < 32; ++jj) {
        // prefetch next row's right + table, and pair two ahead
        float fn = fc; h2x4 Tn = Tc; float4 Rn = Rc;
        if (jj + 1 < 32) {
            float u = sU[jlb + jj + 1];
            int   t = (int)u;
            fn = u - (float)t;
            Tn = *(const h2x4*)(g_tab + t * DPAIR + lane * 4);
            Rn = *(const float4*)&g_right[(size_t)(jb + jj + 1) * DPAIR + lane * 4];
        }
        float4 c = Pc;
        Pc = Pn;
        if (jj + 2 < 32) Pn = __ldcs(pin + (jj + 2) * 32);

        // layernorm stats over 128 channels: quantized partials + REDUX.SUM
        float p1 = c.x + c.y + c.z + c.w;
        float p2 = c.x * c.x + c.y * c.y + c.z * c.z + c.w * c.w;
        int i1 = __reduce_add_sync(0xffffffffu, __float2int_rn(p1 * S1SCL));
        int i2 = __reduce_add_sync(0xffffffffu, __float2int_rn(p2 * S2SCL));
        float s1 = (float)i1 * S1INV;
        float s2 = (float)i2 * S2INV;
        float m    = s1 * (1.0f / 128.0f);
        float var  = fmaf(-m, m, s2 * (1.0f / 128.0f));
        float rstd = rsqrtf(var + 1e-5f);

        // proj via table lerp + left + right
        float2 q0 = __half22float2(Tc.a);
        float2 q1 = __half22float2(Tc.b);
        float2 q2 = __half22float2(Tc.c);
        float2 q3 = __half22float2(Tc.d);
        float4 acc;
        acc.x = Lf.x + Rc.x + fmaf(fc, q0.y - q0.x, q0.x);
        acc.y = Lf.y + Rc.y + fmaf(fc, q1.y - q1.x, q1.x);
        acc.z = Lf.z + Rc.z + fmaf(fc, q2.y - q2.x, q2.x);
        acc.w = Lf.w + Rc.w + fmaf(fc, q3.y - q3.x, q3.x);

        float4 o;
        o.x = fmaf(c.x - m, rstd * G.x, acc.x);
        o.y = fmaf(c.y - m, rstd * G.y, acc.y);
        o.z = fmaf(c.z - m, rstd * G.z, acc.z);
        o.w = fmaf(c.w - m, rstd * G.w, acc.w);
        __stcs(pout + jj * 32, o);

        fc = fn; Tc = Tn; Rc = Rn;
    }
}

// ------------------------------------------------------------------
extern "C" void kernel_launch(void* const* d_in, const int* in_sizes, int n_in,
                              void* d_out, int out_size)
{
    // inputs: 0 seq, 1 msa, 2 pair, 3 xyz, 4 state, 5 W, 6 b_proj,
    //         7 g_state, 8 b_state, 9 g_pair, 10 b_pair, 11 g_msa, 12 b_msa
    const float* msa     = (const float*)d_in[1];
    const float* pair    = (const float*)d_in[2];
    const float* xyz     = (const float*)d_in[3];
    const float* state   = (const float*)d_in[4];
    const float* W       = (const float*)d_in[5];
    const float* b_proj  = (const float*)d_in[6];
    const float* g_state = (const float*)d_in[7];
    const float* b_state = (const float*)d_in[8];
    const float* g_pair  = (const float*)d_in[9];
    const float* b_pair  = (const float*)d_in[10];
    const float* g_msa   = (const float*)d_in[11];
    const float* b_msa   = (const float*)d_in[12];
    float* out = (float*)d_out;

    table_kernel<<<TABN * DPAIR / 256, 256>>>(W);
    prep_kernel<<<L, 128>>>(state, xyz, W, b_proj, g_state, b_state, b_pair,
                            out + STATE_OFF);
    msa_kernel<<<L / 8, 256>>>(msa, g_msa, b_msa, out + MSA_OFF);
    pair_kernel<<<dim3(L, L / JT), 256>>>(pair, g_pair, out + PAIR_OFF);
}

// round 9
// speedup vs baseline: 1.2066x; 1.0207x over previous
#include <cuda_runtime.h>
#include <cuda_fp16.h>
#include <cuda_bf16.h>

// Problem constants (B=1, L=1024, d_msa=256, d_pair=128, d_state=32, 36 RBF bins)
#define L 1024
#define DPAIR 128
#define DMSA 256
#define DSTATE 32
#define JT 256           // j-tile per block in pair kernel
#define TABN 2048        // distance-table entries
#define TABH 0.0125f     // table spacing in D
#define TABSCL 80.0f     // 1/TABH

#define MSA_OFF   0
#define PAIR_OFF  (L * DMSA)                         // 262144
#define STATE_OFF (PAIR_OFF + (size_t)L * L * DPAIR) // 134479872

// fixed-point scales for warp reductions of LN partials
#define S1SCL 32768.0f        // 2^15 for sum(x) partials
#define S1INV (1.0f / 32768.0f)
#define S2SCL 8192.0f         // 2^13 for sum(x^2) partials
#define S2INV (1.0f / 8192.0f)

// ---- device scratch (static: no allocation) ----
__device__ float g_left [L * DPAIR];   // left proj + b_proj + b_pair folded in
__device__ float g_right[L * DPAIR];
__device__ float g_cb   [L * 4];       // Cb xyz (padded)
__device__ float g_tabf [(TABN + 1) * DPAIR];   // pass-1 grid-point values
// g_tab[t*128+p] = half2( proj_p(t*h), proj_p((t+1)*h) )  -- 1 MB
__device__ __half2 g_tab[TABN * DPAIR];

struct alignas(16) h2x4 { __half2 a, b, c, d; };

// classic butterfly (for the small kernels)
__device__ __forceinline__ float warp_sum_shfl(float v) {
    #pragma unroll
    for (int o = 16; o; o >>= 1) v += __shfl_xor_sync(0xffffffffu, v, o);
    return v;
}

// ------------------------------------------------------------------
// Kernel T1: evaluate proj_p(D) at each grid point ONCE, 9-tap window.
// (excluded taps: |D-mu| > ~2.5 -> exp < 5e-10, invisible at 1e-3 tol)
// ------------------------------------------------------------------
__global__ __launch_bounds__(256) void table_pass1_kernel(const float* __restrict__ W) {
    int idx = blockIdx.x * blockDim.x + threadIdx.x;   // t*128 + p
    if (idx >= (TABN + 1) * DPAIR) return;
    int t = idx >> 7, p = idx & 127;
    float D = (float)t * TABH;
    int klo = min(max(__float2int_rn((D - 2.0f) * 1.75f) - 4, 0), 27);
    float s = 0.0f;
    #pragma unroll
    for (int m = 0; m < 9; m++) {
        int k = klo + m;
        float mu = 2.0f + (float)k * (20.0f / 35.0f);   // linspace(2,22,36)
        float a  = (D - mu) * 1.8f;                     // 1/sigma = 36/20
        s = fmaf(__expf(-a * a), W[p * 100 + k], s);
    }
    g_tabf[idx] = s;
}

// ------------------------------------------------------------------
// Kernel T2: pack (t, t+1) pairs into half2 for single-LDG lerp.
// ------------------------------------------------------------------
__global__ __launch_bounds__(256) void table_pass2_kernel() {
    int idx = blockIdx.x * blockDim.x + threadIdx.x;   // t*128 + p
    g_tab[idx] = __floats2half2_rn(g_tabf[idx], g_tabf[idx + DPAIR]);
}

// ------------------------------------------------------------------
// Kernel A: per-residue prep. Block = residue i, 128 threads.
// ------------------------------------------------------------------
__global__ __launch_bounds__(128) void prep_kernel(
    const float* __restrict__ state, const float* __restrict__ xyz,
    const float* __restrict__ W, const float* __restrict__ b_proj,
    const float* __restrict__ g_state, const float* __restrict__ b_state,
    const float* __restrict__ b_pair, float* __restrict__ out_state)
{
    __shared__ float s_sn[DSTATE];
    __shared__ float sWl[128 * 65];   // W[:,36:100], padded stride
    int i = blockIdx.x, tid = threadIdx.x;

    for (int idx = tid; idx < 128 * 64; idx += 128) {
        int p = idx >> 6, k = idx & 63;
        sWl[p * 65 + k] = W[p * 100 + 36 + k];
    }

    if (tid < 32) {
        float x = state[i * DSTATE + tid];
        float s1 = warp_sum_shfl(x);
        float s2 = warp_sum_shfl(x * x);
        float m   = s1 * (1.0f / 32.0f);
        float var = fmaf(-m, m, s2 * (1.0f / 32.0f));
        float sn  = (x - m) * rsqrtf(var + 1e-5f) * g_state[tid] + b_state[tid];
        s_sn[tid] = sn;
        out_state[i * DSTATE + tid] = sn;
    }
    __syncthreads();

    int p = tid;
    float l = b_proj[p] + b_pair[p];
    float r = 0.0f;
    #pragma unroll
    for (int k = 0; k < 32; k++) {
        float s = s_sn[k];
        l = fmaf(s, sWl[p * 65 + k],      l);
        r = fmaf(s, sWl[p * 65 + 32 + k], r);
    }
    g_left [i * DPAIR + p] = l;
    g_right[i * DPAIR + p] = r;

    if (tid == 0) {
        const float* q = xyz + i * 9;
        float bx = q[3] - q[0], by = q[4] - q[1], bz = q[5] - q[2];
        float cx = q[6] - q[3], cy = q[7] - q[4], cz = q[8] - q[5];
        float ax = by * cz - bz * cy;
        float ay = bz * cx - bx * cz;
        float az = bx * cy - by * cx;
        g_cb[i * 4 + 0] = -0.58273431f * ax + 0.56802827f * bx - 0.54067466f * cx + q[3];
        g_cb[i * 4 + 1] = -0.58273431f * ay + 0.56802827f * by - 0.54067466f * cy + q[4];
        g_cb[i * 4 + 2] = -0.58273431f * az + 0.56802827f * bz - 0.54067466f * cz + q[5];
    }
}

// ------------------------------------------------------------------
// Kernel B: msa layernorm (1024 rows x 256). Warp per row.
// ------------------------------------------------------------------
__global__ __launch_bounds__(256) void msa_kernel(
    const float* __restrict__ msa, const float* __restrict__ g,
    const float* __restrict__ b, float* __restrict__ out)
{
    int w = threadIdx.x >> 5, lane = threadIdx.x & 31;
    int r = blockIdx.x * 8 + w;
    const float4* row = (const float4*)(msa + (size_t)r * DMSA);
    float4 a0 = row[lane], a1 = row[lane + 32];
    float s1 = warp_sum_shfl(a0.x + a0.y + a0.z + a0.w + a1.x + a1.y + a1.z + a1.w);
    float s2 = warp_sum_shfl(a0.x * a0.x + a0.y * a0.y + a0.z * a0.z + a0.w * a0.w
                           + a1.x * a1.x + a1.y * a1.y + a1.z * a1.z + a1.w * a1.w);
    float m    = s1 * (1.0f / 256.0f);
    float var  = fmaf(-m, m, s2 * (1.0f / 256.0f));
    float rstd = rsqrtf(var + 1e-5f);
    const float4* G4 = (const float4*)g;
    const float4* B4 = (const float4*)b;
    float4 G0 = G4[lane], G1 = G4[lane + 32];
    float4 B0 = B4[lane], B1 = B4[lane + 32];
    float4 o0, o1;
    o0.x = fmaf((a0.x - m) * rstd, G0.x, B0.x);
    o0.y = fmaf((a0.y - m) * rstd, G0.y, B0.y);
    o0.z = fmaf((a0.z - m) * rstd, G0.z, B0.z);
    o0.w = fmaf((a0.w - m) * rstd, G0.w, B0.w);
    o1.x = fmaf((a1.x - m) * rstd, G1.x, B1.x);
    o1.y = fmaf((a1.y - m) * rstd, G1.y, B1.y);
    o1.z = fmaf((a1.z - m) * rstd, G1.z, B1.z);
    o1.w = fmaf((a1.w - m) * rstd, G1.w, B1.w);
    float4* orow = (float4*)(out + (size_t)r * DMSA);
    orow[lane] = o0; orow[lane + 32] = o1;
}

// ------------------------------------------------------------------
// Kernel C: main pair kernel. Block = (i, jtile); blockIdx.x = i is
// fastest so consecutive blocks on an SM share the jtile (keeps the
// right-tile + table hot in L1/L2). Warp per pair, 4 channels/lane.
// Depth-3 prefetch on the DRAM pair stream (48KB in flight per SM at
// 4 CTAs -> covers ~800cyc DRAM latency), depth-2 on the table,
// right loaded in-iteration (L1/L2 hit).
// ------------------------------------------------------------------
__global__ __launch_bounds__(256, 4) void pair_kernel(
    const float* __restrict__ pair, const float* __restrict__ g_pair,
    float* __restrict__ out_pair)
{
    __shared__ float sU[JT];   // clamped table coordinate per j

    int i   = blockIdx.x;
    int jt0 = blockIdx.y * JT;
    int tid = threadIdx.x;

    // cooperative distance -> table coordinate (thread t handles j = jt0+t)
    {
        int j = jt0 + tid;
        float dx = g_cb[i * 4 + 0] - g_cb[j * 4 + 0];
        float dy = g_cb[i * 4 + 1] - g_cb[j * 4 + 1];
        float dz = g_cb[i * 4 + 2] - g_cb[j * 4 + 2];
        float d2 = dx * dx + dy * dy + dz * dz;
        float D  = sqrtf(fmaxf(d2, 1e-12f));
        sU[tid]  = fminf(D * TABSCL, 2046.999f);
    }
    __syncthreads();

    int w = tid >> 5, lane = tid & 31;
    int jb  = jt0 + w * 32;   // this warp's 32 consecutive j
    int jlb = w * 32;

    float4 Lf = *(const float4*)&g_left[i * DPAIR + lane * 4];  // incl biases
    float4 G  = ((const float4*)g_pair)[lane];

    const float4* pin  = (const float4*)pair    + ((size_t)i * L + jb) * (DPAIR / 4) + lane;
    float4*       pout = (float4*)out_pair      + ((size_t)i * L + jb) * (DPAIR / 4) + lane;
    const float4* rrow = (const float4*)&g_right[(size_t)jb * DPAIR] + lane;

    // ---- prologue: 3 pair rows + table row 0 in flight ----
    float4 P0 = __ldcs(pin);
    float4 P1 = __ldcs(pin + 32);
    float4 P2 = __ldcs(pin + 64);
    float u0 = sU[jlb];
    int   t0 = (int)u0;
    float fc = u0 - (float)t0;
    h2x4  Tc = *(const h2x4*)(g_tab + t0 * DPAIR + lane * 4);

    #pragma unroll 4
    for (int jj = 0; jj < 32; ++jj) {
        float4 c = P0;
        P0 = P1; P1 = P2;
        if (jj + 3 < 32) P2 = __ldcs(pin + (jj + 3) * 32);

        // next row's table entry (depth-2)
        float fn = fc; h2x4 Tn = Tc;
        if (jj + 1 < 32) {
            float u = sU[jlb + jj + 1];
            int   t = (int)u;
            fn = u - (float)t;
            Tn = *(const h2x4*)(g_tab + t * DPAIR + lane * 4);
        }
        // right row: issued early, L1/L2 resident (reused across i-blocks)
        float4 R = rrow[jj * 32];

        // layernorm stats over 128 channels: quantized partials + REDUX.SUM
        float p1 = c.x + c.y + c.z + c.w;
        float p2 = c.x * c.x + c.y * c.y + c.z * c.z + c.w * c.w;
        int i1 = __reduce_add_sync(0xffffffffu, __float2int_rn(p1 * S1SCL));
        int i2 = __reduce_add_sync(0xffffffffu, __float2int_rn(p2 * S2SCL));
        float s1 = (float)i1 * S1INV;
        float s2 = (float)i2 * S2INV;
        float m    = s1 * (1.0f / 128.0f);
        float var  = fmaf(-m, m, s2 * (1.0f / 128.0f));
        float rstd = rsqrtf(var + 1e-5f);

        // proj via table lerp + left + right
        float2 q0 = __half22float2(Tc.a);
        float2 q1 = __half22float2(Tc.b);
        float2 q2 = __half22float2(Tc.c);
        float2 q3 = __half22float2(Tc.d);
        float4 acc;
        acc.x = Lf.x + R.x + fmaf(fc, q0.y - q0.x, q0.x);
        acc.y = Lf.y + R.y + fmaf(fc, q1.y - q1.x, q1.x);
        acc.z = Lf.z + R.z + fmaf(fc, q2.y - q2.x, q2.x);
        acc.w = Lf.w + R.w + fmaf(fc, q3.y - q3.x, q3.x);

        float4 o;
        o.x = fmaf(c.x - m, rstd * G.x, acc.x);
        o.y = fmaf(c.y - m, rstd * G.y, acc.y);
        o.z = fmaf(c.z - m, rstd * G.z, acc.z);
        o.w = fmaf(c.w - m, rstd * G.w, acc.w);
        __stcs(pout + jj * 32, o);

        fc = fn; Tc = Tn;
    }
}

// ------------------------------------------------------------------
extern "C" void kernel_launch(void* const* d_in, const int* in_sizes, int n_in,
                              void* d_out, int out_size)
{
    // inputs: 0 seq, 1 msa, 2 pair, 3 xyz, 4 state, 5 W, 6 b_proj,
    //         7 g_state, 8 b_state, 9 g_pair, 10 b_pair, 11 g_msa, 12 b_msa
    const float* msa     = (const float*)d_in[1];
    const float* pair    = (const float*)d_in[2];
    const float* xyz     = (const float*)d_in[3];
    const float* state   = (const float*)d_in[4];
    const float* W       = (const float*)d_in[5];
    const float* b_proj  = (const float*)d_in[6];
    const float* g_state = (const float*)d_in[7];
    const float* b_state = (const float*)d_in[8];
    const float* g_pair  = (const float*)d_in[9];
    const float* b_pair  = (const float*)d_in[10];
    const float* g_msa   = (const float*)d_in[11];
    const float* b_msa   = (const float*)d_in[12];
    float* out = (float*)d_out;

    table_pass1_kernel<<<((TABN + 1) * DPAIR + 255) / 256, 256>>>(W);
    prep_kernel<<<L, 128>>>(state, xyz, W, b_proj, g_state, b_state, b_pair,
                            out + STATE_OFF);
    table_pass2_kernel<<<TABN * DPAIR / 256, 256>>>();
    msa_kernel<<<L / 8, 256>>>(msa, g_msa, b_msa, out + MSA_OFF);
    pair_kernel<<<dim3(L, L / JT), 256>>>(pair, g_pair, out + PAIR_OFF);
}